// round 3
// baseline (speedup 1.0000x reference)
#include <cuda_runtime.h>
#include <math.h>

// ---------------- problem constants ----------------
#define TOK   32768      // B*H*W tokens
#define CD    512        // channels
#define HWD   1024       // H*W per batch
#define NHEAD 16
#define HD    32
#define NWIN  2048       // B * 64 windows
#define QSTR  1540       // padded smem row stride for staged qkv (1536 + 4 to break bank conflicts)

// ---------------- scratch (__device__ globals, no allocation) ----------------
__device__ float g_xh [TOK * CD];     // [tok, C] transposed input (residual 1)
__device__ float g_xn [TOK * CD];     // LN1 output
__device__ float g_qkv[TOK * 1536];   // qkv projection, token-major
__device__ float g_att[TOK * CD];     // attention output, token-major
__device__ float g_x2 [TOK * CD];     // after proj + residual (residual 2)
__device__ float g_y  [TOK * CD];     // LN2 output, later reused as final z
__device__ float g_h1 [TOK * 2048];   // MLP hidden

// ---------------- transpose: x[B,C,HW] -> xh[B*HW, C] ----------------
__global__ void transpose_in(const float* __restrict__ x, float* __restrict__ xh) {
    __shared__ float tile[32][33];
    int b  = blockIdx.z;
    int c0 = blockIdx.y * 32, p0 = blockIdx.x * 32;
    int tx = threadIdx.x, ty = threadIdx.y;
    #pragma unroll
    for (int i = 0; i < 32; i += 8)
        tile[ty + i][tx] = x[((size_t)b * CD + c0 + ty + i) * HWD + p0 + tx];
    __syncthreads();
    #pragma unroll
    for (int i = 0; i < 32; i += 8)
        xh[((size_t)b * HWD + p0 + ty + i) * CD + c0 + tx] = tile[tx][ty + i];
}

// ---------------- transpose back: z[B*HW, C] -> out[B,C,HW] ----------------
__global__ void transpose_out(const float* __restrict__ z, float* __restrict__ out) {
    __shared__ float tile[32][33];
    int b  = blockIdx.z;
    int c0 = blockIdx.y * 32, p0 = blockIdx.x * 32;
    int tx = threadIdx.x, ty = threadIdx.y;
    #pragma unroll
    for (int i = 0; i < 32; i += 8)
        tile[ty + i][tx] = z[((size_t)b * HWD + p0 + ty + i) * CD + c0 + tx];
    __syncthreads();
    #pragma unroll
    for (int i = 0; i < 32; i += 8)
        out[((size_t)b * CD + c0 + ty + i) * HWD + p0 + tx] = tile[tx][ty + i];
}

// ---------------- LayerNorm over C=512, one warp per row ----------------
__global__ void __launch_bounds__(256) ln_kernel(const float* __restrict__ in,
        const float* __restrict__ w, const float* __restrict__ b,
        float* __restrict__ out) {
    int row  = blockIdx.x * 8 + (threadIdx.x >> 5);
    int lane = threadIdx.x & 31;
    const float4* p = (const float4*)(in + (size_t)row * CD);
    float4 v[4];
    float s = 0.f, s2 = 0.f;
    #pragma unroll
    for (int j = 0; j < 4; j++) {
        v[j] = p[lane + 32 * j];
        s  += v[j].x + v[j].y + v[j].z + v[j].w;
        s2 += v[j].x * v[j].x + v[j].y * v[j].y + v[j].z * v[j].z + v[j].w * v[j].w;
    }
    #pragma unroll
    for (int o = 16; o > 0; o >>= 1) {
        s  += __shfl_xor_sync(0xffffffffu, s,  o);
        s2 += __shfl_xor_sync(0xffffffffu, s2, o);
    }
    float mean = s * (1.f / CD);
    float var  = s2 * (1.f / CD) - mean * mean;
    float rstd = rsqrtf(var + 1e-5f);
    float4* q = (float4*)(out + (size_t)row * CD);
    const float4* wp = (const float4*)w;
    const float4* bp = (const float4*)b;
    #pragma unroll
    for (int j = 0; j < 4; j++) {
        int c4 = lane + 32 * j;
        float4 wv = wp[c4], bv = bp[c4], x = v[j], o;
        o.x = (x.x - mean) * rstd * wv.x + bv.x;
        o.y = (x.y - mean) * rstd * wv.y + bv.y;
        o.z = (x.z - mean) * rstd * wv.z + bv.z;
        o.w = (x.w - mean) * rstd * wv.w + bv.w;
        q[c4] = o;
    }
}

// ---------------- GEMM: C[m,n] = sum_k A[m,k] * W[n,k] + bias[n]  (+epilogue) ---
// EPI: 0 = none, 1 = exact gelu, 2 = add residual res[m*N+n]
__device__ __forceinline__ float gelu_exact(float v) {
    return 0.5f * v * (1.f + erff(v * 0.70710678118654752f));
}

template <int EPI>
__global__ void __launch_bounds__(256, 2) gemm_nt(
        const float* __restrict__ A, const float* __restrict__ W,
        const float* __restrict__ bias, const float* __restrict__ res,
        float* __restrict__ C, int M, int N, int K) {
    __shared__ __align__(16) float As[8][132];
    __shared__ __align__(16) float Ws[8][132];
    const int tid  = threadIdx.x;
    const int bm   = blockIdx.y * 128;
    const int bn   = blockIdx.x * 128;
    const int lrow = tid >> 1;           // 0..127
    const int lk   = (tid & 1) * 4;      // 0 or 4
    const float* Ap = A + (size_t)(bm + lrow) * K + lk;
    const float* Wp = W + (size_t)(bn + lrow) * K + lk;
    const int ty = tid >> 4, tx = tid & 15;

    float acc[8][8];
    #pragma unroll
    for (int i = 0; i < 8; i++)
        #pragma unroll
        for (int j = 0; j < 8; j++) acc[i][j] = 0.f;

    for (int k0 = 0; k0 < K; k0 += 8) {
        float4 av = *(const float4*)(Ap + k0);
        float4 wv = *(const float4*)(Wp + k0);
        __syncthreads();
        As[lk + 0][lrow] = av.x; As[lk + 1][lrow] = av.y;
        As[lk + 2][lrow] = av.z; As[lk + 3][lrow] = av.w;
        Ws[lk + 0][lrow] = wv.x; Ws[lk + 1][lrow] = wv.y;
        Ws[lk + 2][lrow] = wv.z; Ws[lk + 3][lrow] = wv.w;
        __syncthreads();
        #pragma unroll
        for (int k = 0; k < 8; k++) {
            float4 a0 = *(const float4*)&As[k][ty * 8];
            float4 a1 = *(const float4*)&As[k][ty * 8 + 4];
            float4 b0 = *(const float4*)&Ws[k][tx * 8];
            float4 b1 = *(const float4*)&Ws[k][tx * 8 + 4];
            float a[8] = {a0.x, a0.y, a0.z, a0.w, a1.x, a1.y, a1.z, a1.w};
            float b[8] = {b0.x, b0.y, b0.z, b0.w, b1.x, b1.y, b1.z, b1.w};
            #pragma unroll
            for (int i = 0; i < 8; i++)
                #pragma unroll
                for (int j = 0; j < 8; j++)
                    acc[i][j] += a[i] * b[j];
        }
    }

    #pragma unroll
    for (int i = 0; i < 8; i++) {
        int m = bm + ty * 8 + i;
        size_t rowoff = (size_t)m * N + bn + tx * 8;
        #pragma unroll
        for (int jq = 0; jq < 2; jq++) {
            float4 bv = *(const float4*)(bias + bn + tx * 8 + jq * 4);
            float4 o;
            o.x = acc[i][jq * 4 + 0] + bv.x;
            o.y = acc[i][jq * 4 + 1] + bv.y;
            o.z = acc[i][jq * 4 + 2] + bv.z;
            o.w = acc[i][jq * 4 + 3] + bv.w;
            if (EPI == 1) {
                o.x = gelu_exact(o.x); o.y = gelu_exact(o.y);
                o.z = gelu_exact(o.z); o.w = gelu_exact(o.w);
            }
            if (EPI == 2) {
                float4 rv = *(const float4*)(res + rowoff + jq * 4);
                o.x += rv.x; o.y += rv.y; o.z += rv.z; o.w += rv.w;
            }
            *(float4*)(C + rowoff + jq * 4) = o;
        }
    }
}

// ---------------- windowed attention: one block per window, one warp per head --
__global__ void __launch_bounds__(512) attn_kernel(const float* __restrict__ qkv,
        const float* __restrict__ rpb, float* __restrict__ O) {
    extern __shared__ float sm[];
    float* sQ = sm;                  // 16 tokens x QSTR (q | k | v interleaved per token row)
    float* S  = sm + 16 * QSTR;      // 16 heads x 16 x 17
    const int w  = blockIdx.x;
    const int b  = w >> 6, wi = w & 63, wh = wi >> 3, ww = wi & 7;
    const int base = (b * 32 + wh * 4) * 32 + ww * 4;   // token id of local token 0
    const int tid = threadIdx.x;

    // stage this window's 16 qkv rows (1536 floats each) into smem, coalesced
    #pragma unroll
    for (int i = 0; i < 16; i++) {
        int t = base + (i >> 2) * 32 + (i & 3);
        const float* src = qkv + (size_t)t * 1536;
        for (int c = tid; c < 1536; c += 512)
            sQ[i * QSTR + c] = src[c];
    }
    __syncthreads();

    const int head = tid >> 5, lane = tid & 31;
    float* Sh = S + head * 272;   // 16*17

    // phase 1: scores S[i][j] = scale * q_i . k_j + relative position bias
    const float scale = 0.17677669529663689f;   // 1/sqrt(32)
    #pragma unroll
    for (int e = 0; e < 8; e++) {
        int idx = lane * 8 + e;       // 0..255
        int i = idx >> 4, j = idx & 15;
        const float4* qp = (const float4*)(sQ + i * QSTR + head * HD);
        const float4* kp = (const float4*)(sQ + j * QSTR + 512 + head * HD);
        float acc = 0.f;
        #pragma unroll
        for (int d = 0; d < 8; d++) {
            float4 qa = qp[d], kb = kp[d];
            acc += qa.x * kb.x + qa.y * kb.y + qa.z * kb.z + qa.w * kb.w;
        }
        int ri = i >> 2, ci = i & 3, rj = j >> 2, cj = j & 3;
        int bidx = (ri - rj + 3) * 7 + (ci - cj + 3);
        Sh[i * 17 + j] = acc * scale + rpb[bidx * NHEAD + head];
    }
    __syncwarp();

    // phase 2: row softmax (lanes 0..15 each own one row)
    if (lane < 16) {
        float* row = Sh + lane * 17;
        float m = row[0];
        #pragma unroll
        for (int j = 1; j < 16; j++) m = fmaxf(m, row[j]);
        float s = 0.f;
        #pragma unroll
        for (int j = 0; j < 16; j++) { float e = __expf(row[j] - m); row[j] = e; s += e; }
        float inv = 1.f / s;
        #pragma unroll
        for (int j = 0; j < 16; j++) row[j] *= inv;
    }
    __syncwarp();

    // phase 3: O[i][d] = sum_j P[i][j] * v[j][d], lane = d, coalesced store
    #pragma unroll
    for (int i = 0; i < 16; i++) {
        float acc = 0.f;
        #pragma unroll
        for (int j = 0; j < 16; j++)
            acc += Sh[i * 17 + j] * sQ[j * QSTR + 1024 + head * HD + lane];
        int t = base + (i >> 2) * 32 + (i & 3);
        O[(size_t)t * CD + head * HD + lane] = acc;
    }
}

// ---------------- launch ----------------
extern "C" void kernel_launch(void* const* d_in, const int* in_sizes, int n_in,
                              void* d_out, int out_size) {
    const float* x      = (const float*)d_in[0];
    const float* n1w    = (const float*)d_in[1];
    const float* n1b    = (const float*)d_in[2];
    const float* qkv_w  = (const float*)d_in[3];
    const float* qkv_b  = (const float*)d_in[4];
    const float* rpb    = (const float*)d_in[5];
    const float* proj_w = (const float*)d_in[6];
    const float* proj_b = (const float*)d_in[7];
    const float* n2w    = (const float*)d_in[8];
    const float* n2b    = (const float*)d_in[9];
    const float* w1     = (const float*)d_in[10];
    const float* b1     = (const float*)d_in[11];
    const float* w2     = (const float*)d_in[12];
    const float* b2     = (const float*)d_in[13];
    float* out = (float*)d_out;

    float *xh, *xn, *qkvb, *att, *x2, *y, *h1;
    cudaGetSymbolAddress((void**)&xh,   g_xh);
    cudaGetSymbolAddress((void**)&xn,   g_xn);
    cudaGetSymbolAddress((void**)&qkvb, g_qkv);
    cudaGetSymbolAddress((void**)&att,  g_att);
    cudaGetSymbolAddress((void**)&x2,   g_x2);
    cudaGetSymbolAddress((void**)&y,    g_y);
    cudaGetSymbolAddress((void**)&h1,   g_h1);

    const int attn_smem = (16 * QSTR + 16 * 272) * 4;   // 115,968 bytes
    cudaFuncSetAttribute(attn_kernel, cudaFuncAttributeMaxDynamicSharedMemorySize, attn_smem);

    dim3 tb(32, 8);
    // 1) [B,C,HW] -> token-major xh
    transpose_in<<<dim3(32, 16, 32), tb>>>(x, xh);
    // 2) LN1
    ln_kernel<<<TOK / 8, 256>>>(xh, n1w, n1b, xn);
    // 3) QKV projection (token-major): [32768,512] x [1536,512]^T
    gemm_nt<0><<<dim3(12, 256), 256>>>(xn, qkv_w, qkv_b, nullptr, qkvb, TOK, 1536, 512);
    // 4) windowed attention -> token-major att
    attn_kernel<<<NWIN, 512, attn_smem>>>(qkvb, rpb, att);
    // 5) proj + residual(xh) -> x2
    gemm_nt<2><<<dim3(4, 256), 256>>>(att, proj_w, proj_b, xh, x2, TOK, 512, 512);
    // 6) LN2
    ln_kernel<<<TOK / 8, 256>>>(x2, n2w, n2b, y);
    // 7) MLP fc1 + exact GELU
    gemm_nt<1><<<dim3(16, 256), 256>>>(y, w1, b1, nullptr, h1, TOK, 2048, 512);
    // 8) MLP fc2 + residual(x2) -> reuse y as final z
    gemm_nt<2><<<dim3(4, 256), 256>>>(h1, w2, b2, x2, y, TOK, 512, 2048);
    // 9) token-major -> [B,C,HW] output
    transpose_out<<<dim3(32, 16, 32), tb>>>(y, out);
}

// round 8
// speedup vs baseline: 5.6789x; 5.6789x over previous
#include <cuda_runtime.h>
#include <cuda_bf16.h>
#include <math.h>
#include <stdint.h>

// ---------------- problem constants ----------------
#define TOK   32768      // B*H*W tokens
#define CD    512        // channels
#define HWD   1024       // H*W per batch
#define NHEAD 16
#define HD    32
#define NWIN  2048       // B * 64 windows
#define QSTR2 1544       // bf16 elements per staged qkv row (1536 + 8)
#define SSTR  40         // smem row stride in bf16 (32 data + 8 pad) -> 80B, ldmatrix conflict-free

// ---------------- scratch (__device__ globals, no allocation) ----------------
__device__ __align__(16) float         g_xh  [TOK * CD];     // residual 1 (fp32)
__device__ __align__(16) float         g_x2  [TOK * CD];     // residual 2 (fp32)
__device__ __align__(16) float         g_y   [TOK * CD];     // final fp32 (pre-transpose)
__device__ __align__(16) __nv_bfloat16 g_xnb [TOK * CD];     // LN1 out bf16
__device__ __align__(16) __nv_bfloat16 g_qkvb[TOK * 1536];   // qkv bf16
__device__ __align__(16) __nv_bfloat16 g_attb[TOK * CD];     // attention out bf16
__device__ __align__(16) __nv_bfloat16 g_yb  [TOK * CD];     // LN2 out bf16
__device__ __align__(16) __nv_bfloat16 g_h1b [TOK * 2048];   // MLP hidden bf16
__device__ __align__(16) __nv_bfloat16 g_wqkv[1536 * 512];
__device__ __align__(16) __nv_bfloat16 g_wprj[512 * 512];
__device__ __align__(16) __nv_bfloat16 g_w1  [2048 * 512];
__device__ __align__(16) __nv_bfloat16 g_w2  [512 * 2048];

// ---------------- PTX helpers (portable sm_80+ only; NO tcgen05) ----------------
__device__ __forceinline__ uint32_t smem_u32(const void* p) {
    uint32_t a;
    asm("{ .reg .u64 t; cvta.to.shared.u64 t, %1; cvt.u32.u64 %0, t; }" : "=r"(a) : "l"(p));
    return a;
}
__device__ __forceinline__ void ldsm_x4(uint32_t* r, uint32_t addr) {
    asm volatile("ldmatrix.sync.aligned.m8n8.x4.shared.b16 {%0,%1,%2,%3}, [%4];"
        : "=r"(r[0]), "=r"(r[1]), "=r"(r[2]), "=r"(r[3]) : "r"(addr));
}
__device__ __forceinline__ void mma_bf16(float* d, const uint32_t* a, const uint32_t* b) {
    asm volatile("mma.sync.aligned.m16n8k16.row.col.f32.bf16.bf16.f32 "
        "{%0,%1,%2,%3}, {%4,%5,%6,%7}, {%8,%9}, {%0,%1,%2,%3};"
        : "+f"(d[0]), "+f"(d[1]), "+f"(d[2]), "+f"(d[3])
        : "r"(a[0]), "r"(a[1]), "r"(a[2]), "r"(a[3]), "r"(b[0]), "r"(b[1]));
}
__device__ __forceinline__ void cp_async16(uint32_t dst, const void* src) {
    asm volatile("cp.async.cg.shared.global [%0], [%1], 16;" :: "r"(dst), "l"(src));
}
#define CP_COMMIT() asm volatile("cp.async.commit_group;" ::: "memory")
#define CP_WAIT(n)  asm volatile("cp.async.wait_group %0;" :: "n"(n) : "memory")

// ---------------- transposes ----------------
__global__ void transpose_in(const float* __restrict__ x, float* __restrict__ xh) {
    __shared__ float tile[32][33];
    int b = blockIdx.z, c0 = blockIdx.y * 32, p0 = blockIdx.x * 32;
    int tx = threadIdx.x, ty = threadIdx.y;
    #pragma unroll
    for (int i = 0; i < 32; i += 8)
        tile[ty + i][tx] = x[((size_t)b * CD + c0 + ty + i) * HWD + p0 + tx];
    __syncthreads();
    #pragma unroll
    for (int i = 0; i < 32; i += 8)
        xh[((size_t)b * HWD + p0 + ty + i) * CD + c0 + tx] = tile[tx][ty + i];
}
__global__ void transpose_out(const float* __restrict__ z, float* __restrict__ out) {
    __shared__ float tile[32][33];
    int b = blockIdx.z, c0 = blockIdx.y * 32, p0 = blockIdx.x * 32;
    int tx = threadIdx.x, ty = threadIdx.y;
    #pragma unroll
    for (int i = 0; i < 32; i += 8)
        tile[ty + i][tx] = z[((size_t)b * HWD + p0 + ty + i) * CD + c0 + tx];
    __syncthreads();
    #pragma unroll
    for (int i = 0; i < 32; i += 8)
        out[((size_t)b * CD + c0 + ty + i) * HWD + p0 + tx] = tile[tx][ty + i];
}

// ---------------- weight fp32 -> bf16 ----------------
__global__ void wcvt(const float* __restrict__ s, __nv_bfloat16* __restrict__ d, int n) {
    int i = blockIdx.x * 256 + threadIdx.x;
    if (i < n) d[i] = __float2bfloat16(s[i]);
}

// ---------------- LayerNorm (fp32 in -> bf16 out) ----------------
__global__ void __launch_bounds__(256) ln_kernel(const float* __restrict__ in,
        const float* __restrict__ w, const float* __restrict__ b,
        __nv_bfloat16* __restrict__ out) {
    int row  = blockIdx.x * 8 + (threadIdx.x >> 5);
    int lane = threadIdx.x & 31;
    const float4* p = (const float4*)(in + (size_t)row * CD);
    float4 v[4];
    float s = 0.f, s2 = 0.f;
    #pragma unroll
    for (int j = 0; j < 4; j++) {
        v[j] = p[lane + 32 * j];
        s  += v[j].x + v[j].y + v[j].z + v[j].w;
        s2 += v[j].x * v[j].x + v[j].y * v[j].y + v[j].z * v[j].z + v[j].w * v[j].w;
    }
    #pragma unroll
    for (int o = 16; o > 0; o >>= 1) {
        s  += __shfl_xor_sync(0xffffffffu, s,  o);
        s2 += __shfl_xor_sync(0xffffffffu, s2, o);
    }
    float mean = s * (1.f / CD);
    float var  = s2 * (1.f / CD) - mean * mean;
    float rstd = rsqrtf(var + 1e-5f);
    __nv_bfloat16* q = out + (size_t)row * CD;
    const float4* wp = (const float4*)w;
    const float4* bp = (const float4*)b;
    #pragma unroll
    for (int j = 0; j < 4; j++) {
        int c4 = lane + 32 * j;
        float4 wv = wp[c4], bv = bp[c4], x = v[j];
        float ox = (x.x - mean) * rstd * wv.x + bv.x;
        float oy = (x.y - mean) * rstd * wv.y + bv.y;
        float oz = (x.z - mean) * rstd * wv.z + bv.z;
        float ow = (x.w - mean) * rstd * wv.w + bv.w;
        *(__nv_bfloat162*)(q + c4 * 4)     = __floats2bfloat162_rn(ox, oy);
        *(__nv_bfloat162*)(q + c4 * 4 + 2) = __floats2bfloat162_rn(oz, ow);
    }
}

// ---------------- mma.sync bf16 GEMM: C = A[M,K] * W[N,K]^T + bias (+epi) -----
// Block 128x128, 8 warps (2x4), warp tile 64x32, K-chunks of 32, cp.async x2 buf.
// EPI: 0 -> bf16 out; 1 -> gelu -> bf16 out; 2 -> + fp32 residual -> fp32 out.
__device__ __forceinline__ float gelu_exact(float v) {
    return 0.5f * v * (1.f + erff(v * 0.70710678118654752f));
}

template <int EPI>
__global__ void __launch_bounds__(256, 2) gemm_mma(
        const __nv_bfloat16* __restrict__ A, const __nv_bfloat16* __restrict__ Wt,
        const float* __restrict__ bias, const float* __restrict__ res,
        void* __restrict__ Cout, int M, int N, int K) {
    __shared__ __align__(16) __nv_bfloat16 sA[2][128 * SSTR];
    __shared__ __align__(16) __nv_bfloat16 sB[2][128 * SSTR];
    const int tid = threadIdx.x, wid = tid >> 5, lane = tid & 31;
    const int bm = blockIdx.y * 128, bn = blockIdx.x * 128;
    const int wm = (wid >> 2) * 64, wn = (wid & 3) * 32;
    const uint32_t sAa = smem_u32(sA), sBa = smem_u32(sB);
    const uint32_t BUFB = 128 * SSTR * 2;   // bytes per buffer

    float acc[4][4][4];
    #pragma unroll
    for (int i = 0; i < 4; i++)
        #pragma unroll
        for (int j = 0; j < 4; j++)
            #pragma unroll
            for (int q = 0; q < 4; q++) acc[i][j][q] = 0.f;

    const int NC = K >> 5;

    // ---- async tile loader: 1024 x 16B chunks / 256 threads = 4 per thread
    auto issue = [&](int buf, int k0) {
        #pragma unroll
        for (int i = 0; i < 4; i++) {
            int u = tid + i * 256;
            if (u < 512) {
                int r = u >> 2, q = u & 3;
                cp_async16(sAa + buf * BUFB + (uint32_t)(r * SSTR + q * 8) * 2,
                           A + (size_t)(bm + r) * K + k0 + q * 8);
            } else {
                int v = u - 512, r = v >> 2, q = v & 3;
                cp_async16(sBa + buf * BUFB + (uint32_t)(r * SSTR + q * 8) * 2,
                           Wt + (size_t)(bn + r) * K + k0 + q * 8);
            }
        }
        CP_COMMIT();
    };

    issue(0, 0);
    for (int c = 0; c < NC; c++) {
        if (c + 1 < NC) { issue((c + 1) & 1, (c + 1) * 32); CP_WAIT(1); }
        else            { CP_WAIT(0); }
        __syncthreads();
        const uint32_t Ab = sAa + (c & 1) * BUFB;
        const uint32_t Bb = sBa + (c & 1) * BUFB;
        #pragma unroll
        for (int kk = 0; kk < 2; kk++) {
            uint32_t a[4][4], b[4][2];
            #pragma unroll
            for (int mi = 0; mi < 4; mi++) {
                uint32_t row = wm + mi * 16 + (lane & 15);
                uint32_t kb  = kk * 32 + (lane >> 4) * 16;       // bytes
                ldsm_x4(a[mi], Ab + row * (SSTR * 2) + kb);
            }
            #pragma unroll
            for (int nh = 0; nh < 2; nh++) {
                uint32_t r4[4];
                uint32_t nrow = wn + nh * 16 + (lane & 7) + ((lane >> 4) << 3);
                uint32_t kb   = kk * 32 + ((lane >> 3) & 1) * 16;
                ldsm_x4(r4, Bb + nrow * (SSTR * 2) + kb);
                b[nh * 2 + 0][0] = r4[0]; b[nh * 2 + 0][1] = r4[1];
                b[nh * 2 + 1][0] = r4[2]; b[nh * 2 + 1][1] = r4[3];
            }
            #pragma unroll
            for (int mi = 0; mi < 4; mi++)
                #pragma unroll
                for (int ni = 0; ni < 4; ni++)
                    mma_bf16(acc[mi][ni], a[mi], b[ni]);
        }
        __syncthreads();
    }

    // ---- epilogue straight from accumulators
    #pragma unroll
    for (int mi = 0; mi < 4; mi++) {
        #pragma unroll
        for (int half = 0; half < 2; half++) {
            int m = bm + wm + mi * 16 + (lane >> 2) + half * 8;
            #pragma unroll
            for (int ni = 0; ni < 4; ni++) {
                int n = bn + wn + ni * 8 + (lane & 3) * 2;
                float2 bv = *(const float2*)(bias + n);
                float f0 = acc[mi][ni][half * 2 + 0] + bv.x;
                float f1 = acc[mi][ni][half * 2 + 1] + bv.y;
                if (EPI == 1) { f0 = gelu_exact(f0); f1 = gelu_exact(f1); }
                if (EPI == 2) {
                    float2 rv = *(const float2*)(res + (size_t)m * N + n);
                    *(float2*)((float*)Cout + (size_t)m * N + n) =
                        make_float2(f0 + rv.x, f1 + rv.y);
                } else {
                    *(__nv_bfloat162*)((__nv_bfloat16*)Cout + (size_t)m * N + n) =
                        __floats2bfloat162_rn(f0, f1);
                }
            }
        }
    }
}

// ---------------- windowed attention (bf16 in/out, fp32 math) ----------------
__global__ void __launch_bounds__(512) attn_kernel(const __nv_bfloat16* __restrict__ qkv,
        const float* __restrict__ rpb, __nv_bfloat16* __restrict__ O) {
    extern __shared__ char asmem[];
    __nv_bfloat16* sQ = (__nv_bfloat16*)asmem;           // 16 x QSTR2 bf16
    float* S = (float*)(asmem + 16 * QSTR2 * 2);         // 16 heads x 16 x 17
    const int w = blockIdx.x;
    const int b = w >> 6, wi = w & 63, wh = wi >> 3, ww = wi & 7;
    const int base = (b * 32 + wh * 4) * 32 + ww * 4;
    const int tid = threadIdx.x;

    for (int u = tid; u < 16 * 768; u += 512) {
        int i = u / 768; int c = u - i * 768;
        int t = base + (i >> 2) * 32 + (i & 3);
        ((uint32_t*)asmem)[i * 772 + c] = ((const uint32_t*)(qkv + (size_t)t * 1536))[c];
    }
    __syncthreads();

    const int head = tid >> 5, lane = tid & 31;
    float* Sh = S + head * 272;
    const float scale = 0.17677669529663689f;
    #pragma unroll
    for (int e = 0; e < 8; e++) {
        int idx = lane * 8 + e;
        int i = idx >> 4, j = idx & 15;
        const __nv_bfloat162* qp = (const __nv_bfloat162*)(sQ + i * QSTR2 + head * HD);
        const __nv_bfloat162* kp = (const __nv_bfloat162*)(sQ + j * QSTR2 + 512 + head * HD);
        float acc = 0.f;
        #pragma unroll
        for (int d = 0; d < 16; d++) {
            float2 qa = __bfloat1622float2(qp[d]);
            float2 kb = __bfloat1622float2(kp[d]);
            acc += qa.x * kb.x + qa.y * kb.y;
        }
        int ri = i >> 2, ci = i & 3, rj = j >> 2, cj = j & 3;
        int bidx = (ri - rj + 3) * 7 + (ci - cj + 3);
        Sh[i * 17 + j] = acc * scale + rpb[bidx * NHEAD + head];
    }
    __syncwarp();
    if (lane < 16) {
        float* row = Sh + lane * 17;
        float m = row[0];
        #pragma unroll
        for (int j = 1; j < 16; j++) m = fmaxf(m, row[j]);
        float s = 0.f;
        #pragma unroll
        for (int j = 0; j < 16; j++) { float e = __expf(row[j] - m); row[j] = e; s += e; }
        float inv = 1.f / s;
        #pragma unroll
        for (int j = 0; j < 16; j++) row[j] *= inv;
    }
    __syncwarp();
    #pragma unroll
    for (int i = 0; i < 16; i++) {
        float acc = 0.f;
        #pragma unroll
        for (int j = 0; j < 16; j++)
            acc += Sh[i * 17 + j] * __bfloat162float(sQ[j * QSTR2 + 1024 + head * HD + lane]);
        int t = base + (i >> 2) * 32 + (i & 3);
        O[(size_t)t * CD + head * HD + lane] = __float2bfloat16(acc);
    }
}

// ---------------- launch ----------------
extern "C" void kernel_launch(void* const* d_in, const int* in_sizes, int n_in,
                              void* d_out, int out_size) {
    const float* x      = (const float*)d_in[0];
    const float* n1w    = (const float*)d_in[1];
    const float* n1b    = (const float*)d_in[2];
    const float* qkv_w  = (const float*)d_in[3];
    const float* qkv_b  = (const float*)d_in[4];
    const float* rpb    = (const float*)d_in[5];
    const float* proj_w = (const float*)d_in[6];
    const float* proj_b = (const float*)d_in[7];
    const float* n2w    = (const float*)d_in[8];
    const float* n2b    = (const float*)d_in[9];
    const float* w1     = (const float*)d_in[10];
    const float* b1     = (const float*)d_in[11];
    const float* w2     = (const float*)d_in[12];
    const float* b2     = (const float*)d_in[13];
    float* out = (float*)d_out;

    float *xh, *x2, *y;
    __nv_bfloat16 *xnb, *qkvb, *attb, *yb, *h1b, *wqkv, *wprj, *w1b, *w2b;
    cudaGetSymbolAddress((void**)&xh,   g_xh);
    cudaGetSymbolAddress((void**)&x2,   g_x2);
    cudaGetSymbolAddress((void**)&y,    g_y);
    cudaGetSymbolAddress((void**)&xnb,  g_xnb);
    cudaGetSymbolAddress((void**)&qkvb, g_qkvb);
    cudaGetSymbolAddress((void**)&attb, g_attb);
    cudaGetSymbolAddress((void**)&yb,   g_yb);
    cudaGetSymbolAddress((void**)&h1b,  g_h1b);
    cudaGetSymbolAddress((void**)&wqkv, g_wqkv);
    cudaGetSymbolAddress((void**)&wprj, g_wprj);
    cudaGetSymbolAddress((void**)&w1b,  g_w1);
    cudaGetSymbolAddress((void**)&w2b,  g_w2);

    const int attn_smem = 16 * QSTR2 * 2 + 16 * 272 * 4;   // 66816 bytes
    cudaFuncSetAttribute(attn_kernel, cudaFuncAttributeMaxDynamicSharedMemorySize, attn_smem);

    dim3 tb(32, 8);
    transpose_in<<<dim3(32, 16, 32), tb>>>(x, xh);
    wcvt<<<(1536 * 512 + 255) / 256, 256>>>(qkv_w,  wqkv, 1536 * 512);
    wcvt<<<(512  * 512 + 255) / 256, 256>>>(proj_w, wprj, 512 * 512);
    wcvt<<<(2048 * 512 + 255) / 256, 256>>>(w1,     w1b,  2048 * 512);
    wcvt<<<(512 * 2048 + 255) / 256, 256>>>(w2,     w2b,  512 * 2048);

    ln_kernel<<<TOK / 8, 256>>>(xh, n1w, n1b, xnb);
    gemm_mma<0><<<dim3(12, 256), 256>>>(xnb, wqkv, qkv_b, nullptr, qkvb, TOK, 1536, 512);
    attn_kernel<<<NWIN, 512, attn_smem>>>(qkvb, rpb, attb);
    gemm_mma<2><<<dim3(4, 256), 256>>>(attb, wprj, proj_b, xh, x2, TOK, 512, 512);
    ln_kernel<<<TOK / 8, 256>>>(x2, n2w, n2b, yb);
    gemm_mma<1><<<dim3(16, 256), 256>>>(yb, w1b, b1, nullptr, h1b, TOK, 2048, 512);
    gemm_mma<2><<<dim3(4, 256), 256>>>(h1b, w2b, b2, x2, y, TOK, 512, 2048);
    transpose_out<<<dim3(32, 16, 32), tb>>>(y, out);
}